// round 6
// baseline (speedup 1.0000x reference)
#include <cuda_runtime.h>
#include <cstdint>

// SpikeFP32ScaleBy2K — rows of 32 {0,1} floats = big-endian FP32 bit pattern.
// out = x with exponent += K (mod 256), K = 8-bit two's-complement
// (0x80|m_k[0..6]) >> (7 - ((e_k-127)&7)), negated if s_k; passthrough when
// k's exp+mantissa bits are all zero. Only elements 1..8 change.
//
// R6: element-order combined word, ONE 3-step shfl_xor OR-butterfly per
// 4-row group, bit-reversals done once on the broadcast scalar, output via
// 16-entry SMEM LUT (nibble -> float4). 32-bit indexing throughout.
//
// Combined word C (element-order, bit = element value):
//   [0:12)   x elements 0..11   (lanes c=0..2; only bits 1..8 consumed)
//   [12:28)  k elements 0..15   (lanes c=0..3)
//   [28]     OR of k elements 16..31 (lanes c=4..7)

static constexpr int GROUPS = 2;                 // 4 rows/group, 8 rows/warp
static constexpr unsigned ONEF = 0x3F800000u;

__device__ __forceinline__ unsigned pack_nib(uint4 u) {
    // components are exactly 0x00000000 or 0x3F800000
    unsigned a = min(u.x, 1u), b = min(u.y, 1u);
    unsigned c = min(u.z, 1u), d = min(u.w, 1u);
    return a | (b << 1) | (c << 2) | (d << 3);
}

__global__ void __launch_bounds__(256)
spike_scale_kernel(const uint4* __restrict__ x4,
                   const uint4* __restrict__ k4,
                   uint4* __restrict__ out4,
                   unsigned nrows) {
    __shared__ uint4 lut[16];
    if (threadIdx.x < 16) {
        unsigned n = threadIdx.x;
        lut[n] = make_uint4((n & 1u) * ONEF, ((n >> 1) & 1u) * ONEF,
                            ((n >> 2) & 1u) * ONEF, ((n >> 3) & 1u) * ONEF);
    }
    __syncthreads();

    const unsigned lane = threadIdx.x & 31u;
    const unsigned c    = lane & 7u;             // float4 chunk within row
    const unsigned sub  = lane >> 3;             // row within 4-row group
    const unsigned s4   = c * 4u;                // first element idx of chunk

    // per-lane constants
    const unsigned Ax   = (c <= 2u) ? (0xFu << s4) : 0u;        // x field
    const unsigned Ak   = (c <= 3u) ? (0xFu << (s4 + 12u)) : 0u;// k field
    const unsigned s4k  = (s4 + 12u) & 31u;
    const unsigned m0   = (c >= 4u) ? ~0u : 0u;  // k hi-half OR contributor
    const unsigned remm = (c == 0u) ? 0xEu : (c == 1u) ? 0xFu
                        : (c == 2u) ? 0x1u : 0u; // exponent components
    const unsigned sh_e = (23u + s4) & 31u;      // enew-bit slice position

    const unsigned warp_id = blockIdx.x * (blockDim.x >> 5) + (threadIdx.x >> 5);
    const unsigned row0 = warp_id * (4u * GROUPS);
    if (row0 >= nrows) return;                   // warp-uniform (after sync)

    uint4 xv[GROUPS], kv[GROUPS];
    unsigned idx[GROUPS], safem[GROUPS];
    const bool full = (row0 + 4u * GROUPS) <= nrows;

    #pragma unroll
    for (int g = 0; g < GROUPS; g++) {
        unsigned row = row0 + 4u * g + sub;
        unsigned ok  = full | (row < nrows);
        safem[g] = 0u - (unsigned)ok;
        unsigned r = ok ? row : (nrows - 1u);    // clamp keeps loads in-bounds
        idx[g] = r * 8u + c;                     // max 2^24, fits 32-bit
        xv[g] = x4[idx[g]];
        kv[g] = k4[idx[g]];
    }

    #pragma unroll
    for (int g = 0; g < GROUPS; g++) {
        unsigned nibX = pack_nib(xv[g]);
        unsigned nibK = pack_nib(kv[g]);
        unsigned kOr  = (kv[g].x | kv[g].y | kv[g].z | kv[g].w) & m0;

        unsigned C = ((nibX << s4) & Ax)
                   | ((nibK << s4k) & Ak)
                   | (min(kOr, 1u) << 28);

        C |= __shfl_xor_sync(~0u, C, 1);         // OR-butterfly (8-lane group)
        C |= __shfl_xor_sync(~0u, C, 2);
        C |= __shfl_xor_sync(~0u, C, 4);

        // ── scalar circuit (all reversals on the broadcast word) ──
        unsigned B    = __brev(C);
        unsigned ex   = (B >> 23) & 0xFFu;       // x elements 1..8, LSB=elem8
        unsigned ek   = (B >> 11) & 0xFFu;       // k elements 1..8
        unsigned val  = 0x80u | ((B >> 4) & 0x7Fu);   // 1.m_k[0..6]
        unsigned rs   = (6u - ek) & 7u;          // = 7 - ((ek-127)&7)
        unsigned kabs = val >> rs;
        unsigned neg  = 0u - ((C >> 12) & 1u);   // s_k
        unsigned kf   = (kabs ^ neg) - neg;
        unsigned enew = ex + kf;                 // low 8 bits valid
        unsigned knz4 = (C & 0x1FFFE000u) ? 0xFu : 0u;  // k exp|mant nonzero

        // ── per-lane output nibble: enew bits for exponent comps,
        //    own nibX for everything else ──
        unsigned sel    = remm & knz4;
        unsigned en_nib = __brev(enew) >> sh_e;  // bit t = enew bit (8-s4-t)
        unsigned no     = (en_nib & sel) | (nibX & ~sel);

        uint4 o = lut[no & 0xFu];
        if (safem[g]) out4[idx[g]] = o;
    }
}

extern "C" void kernel_launch(void* const* d_in, const int* in_sizes, int n_in,
                              void* d_out, int out_size) {
    const uint4* x4 = (const uint4*)d_in[0];
    const uint4* k4 = (const uint4*)d_in[1];
    uint4* out4 = (uint4*)d_out;

    unsigned nrows = (unsigned)(in_sizes[0] / 32);

    const int threads = 256;                     // 8 warps
    const int rows_per_block = 8 * 4 * GROUPS;   // 64
    int blocks = (int)((nrows + rows_per_block - 1) / rows_per_block);

    spike_scale_kernel<<<blocks, threads>>>(x4, k4, out4, nrows);
}